// round 6
// baseline (speedup 1.0000x reference)
#include <cuda_runtime.h>
#include <cuda_bf16.h>
#include <math.h>

#define B_ 64
#define W_ 4096
#define H_ 128
#define I_ 128
#define CHUNKS 8
#define TPB (W_ / CHUNKS)
#define WARPS 8
#define ROWS_PER_WARP (TPB / WARPS)   // 64

__device__ float g_pm[B_ * CHUNKS];
__device__ float g_pl[B_ * CHUNKS];
__device__ float g_pacc[B_ * CHUNKS * H_];

// Transposed activations [k][b]
__device__ float g_xcatT[(H_ + I_) * B_];
__device__ float g_xinT[I_ * B_];
__device__ float g_h1T[H_ * B_];
__device__ float g_h0T0[H_ * B_];
__device__ float g_h0T1[H_ * B_];

__device__ __forceinline__ float warp_sum(float v) {
    #pragma unroll
    for (int o = 16; o; o >>= 1) v += __shfl_xor_sync(0xffffffffu, v, o);
    return v;
}

__device__ __forceinline__ float sigm(float x) { return 1.0f / (1.0f + expf(-x)); }

// ---------------------------------------------------------------------------
// Phase 1: fused score + online-softmax weighted accumulate, one encoder pass.
// Each warp: 64 rows as 32 pairs; half-warp hw handles row 2*it+hw.
// Per lane: 8 columns (2 float4). Score reduced over 16 lanes (4 SHFL);
// one shfl_xor(16) exchanges scores to resolve logit(r) = score(r-1) + bias.
// ---------------------------------------------------------------------------
__global__ __launch_bounds__(256, 4)
void attn_partial_kernel(const float* __restrict__ enc,
                         const float* __restrict__ h0,
                         const float* __restrict__ c0,
                         const float* __restrict__ attW,
                         const float* __restrict__ attB)
{
    const int c    = blockIdx.x;
    const int b    = blockIdx.y;
    const int tid  = threadIdx.x;
    const int warp = tid >> 5;
    const int lane = tid & 31;
    const int hw   = lane >> 4;    // half-warp id
    const int sl   = lane & 15;    // sub-lane

    __shared__ float s_red[WARPS];
    __shared__ float s_bias;
    __shared__ float s_m[2 * WARPS], s_l[2 * WARPS];
    __shared__ float s_acc[2 * WARPS][H_];

    // per-batch bias
    float part = 0.f;
    if (tid < H_) {
        float hs = h0[(1 * B_ + b) * H_ + tid];
        float cs = c0[(1 * B_ + b) * H_ + tid];
        part = hs * cs * attW[H_ + tid];
    }
    part = warp_sum(part);
    if (lane == 0) s_red[warp] = part;
    __syncthreads();
    if (tid == 0) {
        float s = 0.f;
        #pragma unroll
        for (int w = 0; w < WARPS; w++) s += s_red[w];
        s_bias = s + attB[0];
    }
    __syncthreads();
    const float bias = s_bias;

    const float4 wa0 = *reinterpret_cast<const float4*>(attW + sl * 8);
    const float4 wa1 = *reinterpret_cast<const float4*>(attW + sl * 8 + 4);

    const int rowStart = c * TPB + warp * ROWS_PER_WARP;
    const float* encb = enc + (size_t)b * W_ * H_;

    // prologue: carry = logit of row rowStart (only hw0 consumes it)
    float carry;
    if (rowStart == 0) {
        carry = 0.0f;
    } else {
        const float* pr = encb + (size_t)(rowStart - 1) * H_ + sl * 8;
        float4 u0 = *reinterpret_cast<const float4*>(pr);
        float4 u1 = *reinterpret_cast<const float4*>(pr + 4);
        float d = u0.x * wa0.x + u0.y * wa0.y + u0.z * wa0.z + u0.w * wa0.w
                + u1.x * wa1.x + u1.y * wa1.y + u1.z * wa1.z + u1.w * wa1.w;
        #pragma unroll
        for (int o = 8; o; o >>= 1) d += __shfl_xor_sync(0xffffffffu, d, o);
        carry = d + bias;
    }

    float m = -1e30f, l = 0.f;
    float a0x = 0.f, a0y = 0.f, a0z = 0.f, a0w = 0.f;
    float a1x = 0.f, a1y = 0.f, a1z = 0.f, a1w = 0.f;

    const float* rp = encb + (size_t)(rowStart + hw) * H_ + sl * 8;
    #pragma unroll 2
    for (int it = 0; it < ROWS_PER_WARP / 2; it++) {
        const float4 v0 = *reinterpret_cast<const float4*>(rp);
        const float4 v1 = *reinterpret_cast<const float4*>(rp + 4);
        rp += 2 * H_;
        float d = v0.x * wa0.x + v0.y * wa0.y + v0.z * wa0.z + v0.w * wa0.w
                + v1.x * wa1.x + v1.y * wa1.y + v1.z * wa1.z + v1.w * wa1.w;
        #pragma unroll
        for (int o = 8; o; o >>= 1) d += __shfl_xor_sync(0xffffffffu, d, o);
        // exchange scores between half-warps
        const float x = __shfl_xor_sync(0xffffffffu, d, 16);
        float logit;
        if (hw == 0) { logit = carry; carry = x + bias; }
        else         { logit = x + bias; }
        // online softmax update
        const float mNew = fmaxf(m, logit);
        const float corr = __expf(m - mNew);
        const float p    = __expf(logit - mNew);
        l   = l   * corr + p;
        a0x = a0x * corr + p * v0.x;
        a0y = a0y * corr + p * v0.y;
        a0z = a0z * corr + p * v0.z;
        a0w = a0w * corr + p * v0.w;
        a1x = a1x * corr + p * v1.x;
        a1y = a1y * corr + p * v1.y;
        a1z = a1z * corr + p * v1.z;
        a1w = a1w * corr + p * v1.w;
        m = mNew;
    }

    const int idx = warp * 2 + hw;
    if (sl == 0) { s_m[idx] = m; s_l[idx] = l; }
    s_acc[idx][sl * 8 + 0] = a0x;
    s_acc[idx][sl * 8 + 1] = a0y;
    s_acc[idx][sl * 8 + 2] = a0z;
    s_acc[idx][sl * 8 + 3] = a0w;
    s_acc[idx][sl * 8 + 4] = a1x;
    s_acc[idx][sl * 8 + 5] = a1y;
    s_acc[idx][sl * 8 + 6] = a1z;
    s_acc[idx][sl * 8 + 7] = a1w;
    __syncthreads();

    // block combine: 16 half-warp partials -> one chunk partial
    if (tid < H_) {
        float M = s_m[0];
        #pragma unroll
        for (int w = 1; w < 2 * WARPS; w++) M = fmaxf(M, s_m[w]);
        float L = 0.f, A = 0.f;
        #pragma unroll
        for (int w = 0; w < 2 * WARPS; w++) {
            const float e = __expf(s_m[w] - M);
            L += s_l[w] * e;
            A += s_acc[w][tid] * e;
        }
        const int pi = b * CHUNKS + c;
        g_pacc[pi * H_ + tid] = A;
        if (tid == 0) { g_pm[pi] = M; g_pl[pi] = L; }
    }
}

// ---------------------------------------------------------------------------
// K2: combine chunk partials -> xcatT; transpose h0 states.
// ---------------------------------------------------------------------------
__global__ __launch_bounds__(256)
void combine_kernel(const float* __restrict__ input,
                    const float* __restrict__ h0)
{
    const int b = blockIdx.x;
    const int k = threadIdx.x;

    if (k < H_) {
        float M = g_pm[b * CHUNKS + 0];
        #pragma unroll
        for (int cc = 1; cc < CHUNKS; cc++) M = fmaxf(M, g_pm[b * CHUNKS + cc]);
        float L = 0.f, A = 0.f;
        #pragma unroll
        for (int cc = 0; cc < CHUNKS; cc++) {
            const float e = __expf(g_pm[b * CHUNKS + cc] - M);
            L += g_pl[b * CHUNKS + cc] * e;
            A += g_pacc[(b * CHUNKS + cc) * H_ + k] * e;
        }
        g_xcatT[k * B_ + b] = A / L;
        g_h0T0[k * B_ + b] = h0[(0 * B_ + b) * H_ + k];
        g_h0T1[k * B_ + b] = h0[(1 * B_ + b) * H_ + k];
    } else {
        g_xcatT[k * B_ + b] = input[b * I_ + (k - H_)];
    }
}

// ---------------------------------------------------------------------------
// K3: xin GEMV. grid = 32 blocks (4 j each), 256 threads:
// bq = tid&15 (4 b's via float4), kq = (tid>>4)&3 (64 k's), jl = tid>>6.
// ---------------------------------------------------------------------------
__global__ __launch_bounds__(256)
void xin_kernel(const float* __restrict__ inp_W,
                const float* __restrict__ inp_b)
{
    const int tid = threadIdx.x;
    const int bq  = tid & 15;
    const int kq  = (tid >> 4) & 3;
    const int jl  = tid >> 6;
    const int b0  = bq * 4;

    __shared__ float s_w[4][H_ + I_];     // 4 rows x 256
    __shared__ float s_p[4][4][B_];       // [kq][jl][b]
    __shared__ float s_o[4][B_];

    // stage 4 contiguous weight rows (1024 floats = 256 float4)
    {
        const float4* src = reinterpret_cast<const float4*>(inp_W + blockIdx.x * 4 * (H_ + I_));
        reinterpret_cast<float4*>(&s_w[0][0])[tid] = src[tid];
    }
    __syncthreads();

    const float* wp = &s_w[jl][kq * 64];
    const float* ap = &g_xcatT[kq * 64 * B_ + b0];
    float ax = 0.f, ay = 0.f, az = 0.f, aw = 0.f;
    #pragma unroll
    for (int t = 0; t < 64; t += 8) {
        float4 v0 = *reinterpret_cast<const float4*>(ap + (t + 0) * B_);
        float4 v1 = *reinterpret_cast<const float4*>(ap + (t + 1) * B_);
        float4 v2 = *reinterpret_cast<const float4*>(ap + (t + 2) * B_);
        float4 v3 = *reinterpret_cast<const float4*>(ap + (t + 3) * B_);
        float4 v4 = *reinterpret_cast<const float4*>(ap + (t + 4) * B_);
        float4 v5 = *reinterpret_cast<const float4*>(ap + (t + 5) * B_);
        float4 v6 = *reinterpret_cast<const float4*>(ap + (t + 6) * B_);
        float4 v7 = *reinterpret_cast<const float4*>(ap + (t + 7) * B_);
        float w0 = wp[t + 0], w1 = wp[t + 1], w2 = wp[t + 2], w3 = wp[t + 3];
        float w4 = wp[t + 4], w5 = wp[t + 5], w6 = wp[t + 6], w7 = wp[t + 7];
        ax = fmaf(w0, v0.x, ax); ay = fmaf(w0, v0.y, ay); az = fmaf(w0, v0.z, az); aw = fmaf(w0, v0.w, aw);
        ax = fmaf(w1, v1.x, ax); ay = fmaf(w1, v1.y, ay); az = fmaf(w1, v1.z, az); aw = fmaf(w1, v1.w, aw);
        ax = fmaf(w2, v2.x, ax); ay = fmaf(w2, v2.y, ay); az = fmaf(w2, v2.z, az); aw = fmaf(w2, v2.w, aw);
        ax = fmaf(w3, v3.x, ax); ay = fmaf(w3, v3.y, ay); az = fmaf(w3, v3.z, az); aw = fmaf(w3, v3.w, aw);
        ax = fmaf(w4, v4.x, ax); ay = fmaf(w4, v4.y, ay); az = fmaf(w4, v4.z, az); aw = fmaf(w4, v4.w, aw);
        ax = fmaf(w5, v5.x, ax); ay = fmaf(w5, v5.y, ay); az = fmaf(w5, v5.z, az); aw = fmaf(w5, v5.w, aw);
        ax = fmaf(w6, v6.x, ax); ay = fmaf(w6, v6.y, ay); az = fmaf(w6, v6.z, az); aw = fmaf(w6, v6.w, aw);
        ax = fmaf(w7, v7.x, ax); ay = fmaf(w7, v7.y, ay); az = fmaf(w7, v7.z, az); aw = fmaf(w7, v7.w, aw);
    }
    s_p[kq][jl][b0 + 0] = ax;
    s_p[kq][jl][b0 + 1] = ay;
    s_p[kq][jl][b0 + 2] = az;
    s_p[kq][jl][b0 + 3] = aw;
    __syncthreads();

    // reduce: 256 threads = (jl2, b)
    {
        const int jl2 = tid >> 6;
        const int bb  = tid & 63;
        float s = s_p[0][jl2][bb] + s_p[1][jl2][bb] + s_p[2][jl2][bb] + s_p[3][jl2][bb];
        g_xinT[(blockIdx.x * 4 + jl2) * B_ + bb] = s + inp_b[blockIdx.x * 4 + jl2];
    }
}

// ---------------------------------------------------------------------------
// K4/K5: LSTM cell. grid = H_ blocks (h), 256 threads:
// bq = tid&15 (4 b's via float4), kq = (tid>>4)&3 (64 of 256 k's), gate = tid>>6.
// kq 0,1 -> x-part (xT), kq 2,3 -> h-part (hT).
// ---------------------------------------------------------------------------
__global__ __launch_bounds__(256)
void lstm_cell_kernel(const float* __restrict__ xT,
                      const float* __restrict__ hT,
                      const float* __restrict__ W_ih,
                      const float* __restrict__ W_hh,
                      const float* __restrict__ b_ih,
                      const float* __restrict__ b_hh,
                      const float* __restrict__ cPrev,
                      float* __restrict__ outH,
                      float* __restrict__ outH2,
                      float* __restrict__ outC,
                      float* __restrict__ hT_out)
{
    const int h    = blockIdx.x;
    const int tid  = threadIdx.x;
    const int bq   = tid & 15;
    const int kq   = (tid >> 4) & 3;
    const int gate = tid >> 6;
    const int b0   = bq * 4;

    __shared__ float s_w[4][2 * H_];    // [gate][ W_ih row | W_hh row ]
    __shared__ float s_p[4][4][B_];     // [kq][gate][b]
    __shared__ float s_g[4][B_];

    // stage weights: 1024 floats = 256 float4, one per thread
    {
        const int g = tid >> 6;          // 4 float4-slots groups of 64
        const int q = tid & 63;          // slot within gate (64 float4 = 256 floats)
        const float4* src = (q < 32)
            ? reinterpret_cast<const float4*>(W_ih + (g * H_ + h) * H_) + q
            : reinterpret_cast<const float4*>(W_hh + (g * H_ + h) * H_) + (q - 32);
        reinterpret_cast<float4*>(&s_w[g][0])[q] = *src;
    }
    __syncthreads();

    const float* wp = &s_w[gate][kq * 64];
    const float* ap = (kq < 2) ? (xT + (kq * 64) * B_ + b0)
                               : (hT + ((kq - 2) * 64) * B_ + b0);
    float ax = 0.f, ay = 0.f, az = 0.f, aw = 0.f;
    #pragma unroll
    for (int t = 0; t < 64; t += 8) {
        float4 v0 = *reinterpret_cast<const float4*>(ap + (t + 0) * B_);
        float4 v1 = *reinterpret_cast<const float4*>(ap + (t + 1) * B_);
        float4 v2 = *reinterpret_cast<const float4*>(ap + (t + 2) * B_);
        float4 v3 = *reinterpret_cast<const float4*>(ap + (t + 3) * B_);
        float4 v4 = *reinterpret_cast<const float4*>(ap + (t + 4) * B_);
        float4 v5 = *reinterpret_cast<const float4*>(ap + (t + 5) * B_);
        float4 v6 = *reinterpret_cast<const float4*>(ap + (t + 6) * B_);
        float4 v7 = *reinterpret_cast<const float4*>(ap + (t + 7) * B_);
        float w0 = wp[t + 0], w1 = wp[t + 1], w2 = wp[t + 2], w3 = wp[t + 3];
        float w4 = wp[t + 4], w5 = wp[t + 5], w6 = wp[t + 6], w7 = wp[t + 7];
        ax = fmaf(w0, v0.x, ax); ay = fmaf(w0, v0.y, ay); az = fmaf(w0, v0.z, az); aw = fmaf(w0, v0.w, aw);
        ax = fmaf(w1, v1.x, ax); ay = fmaf(w1, v1.y, ay); az = fmaf(w1, v1.z, az); aw = fmaf(w1, v1.w, aw);
        ax = fmaf(w2, v2.x, ax); ay = fmaf(w2, v2.y, ay); az = fmaf(w2, v2.z, az); aw = fmaf(w2, v2.w, aw);
        ax = fmaf(w3, v3.x, ax); ay = fmaf(w3, v3.y, ay); az = fmaf(w3, v3.z, az); aw = fmaf(w3, v3.w, aw);
        ax = fmaf(w4, v4.x, ax); ay = fmaf(w4, v4.y, ay); az = fmaf(w4, v4.z, az); aw = fmaf(w4, v4.w, aw);
        ax = fmaf(w5, v5.x, ax); ay = fmaf(w5, v5.y, ay); az = fmaf(w5, v5.z, az); aw = fmaf(w5, v5.w, aw);
        ax = fmaf(w6, v6.x, ax); ay = fmaf(w6, v6.y, ay); az = fmaf(w6, v6.z, az); aw = fmaf(w6, v6.w, aw);
        ax = fmaf(w7, v7.x, ax); ay = fmaf(w7, v7.y, ay); az = fmaf(w7, v7.z, az); aw = fmaf(w7, v7.w, aw);
    }
    s_p[kq][gate][b0 + 0] = ax;
    s_p[kq][gate][b0 + 1] = ay;
    s_p[kq][gate][b0 + 2] = az;
    s_p[kq][gate][b0 + 3] = aw;
    __syncthreads();

    // reduce: 256 threads = (gate2, b)
    {
        const int g2 = tid >> 6;
        const int bb = tid & 63;
        const int j  = g2 * H_ + h;
        float s = s_p[0][g2][bb] + s_p[1][g2][bb] + s_p[2][g2][bb] + s_p[3][g2][bb];
        s_g[g2][bb] = s + b_ih[j] + b_hh[j];
    }
    __syncthreads();

    if (tid < B_) {
        const int bb = tid;
        const float gi = s_g[0][bb];
        const float gf = s_g[1][bb];
        const float gg = s_g[2][bb];
        const float go = s_g[3][bb];
        const float cp = cPrev[bb * H_ + h];
        const float cN = sigm(gf) * cp + sigm(gi) * tanhf(gg);
        const float hN = sigm(go) * tanhf(cN);
        outH[bb * H_ + h] = hN;
        if (outH2) outH2[bb * H_ + h] = hN;
        outC[bb * H_ + h] = cN;
        if (hT_out) hT_out[h * B_ + bb] = hN;
    }
}

extern "C" void kernel_launch(void* const* d_in, const int* in_sizes, int n_in,
                              void* d_out, int out_size) {
    const float* input  = (const float*)d_in[0];
    const float* h0     = (const float*)d_in[1];
    const float* c0     = (const float*)d_in[2];
    const float* enc    = (const float*)d_in[3];
    const float* attW   = (const float*)d_in[4];
    const float* attB   = (const float*)d_in[5];
    const float* inp_W  = (const float*)d_in[6];
    const float* inp_b  = (const float*)d_in[7];
    const float* W_ih0  = (const float*)d_in[8];
    const float* W_hh0  = (const float*)d_in[9];
    const float* b_ih0  = (const float*)d_in[10];
    const float* b_hh0  = (const float*)d_in[11];
    const float* W_ih1  = (const float*)d_in[12];
    const float* W_hh1  = (const float*)d_in[13];
    const float* b_ih1  = (const float*)d_in[14];
    const float* b_hh1  = (const float*)d_in[15];
    float* out = (float*)d_out;

    float* out_y  = out + 0 * B_ * H_;
    float* out_h1 = out + 1 * B_ * H_;
    float* out_h2 = out + 2 * B_ * H_;
    float* out_c1 = out + 3 * B_ * H_;
    float* out_c2 = out + 4 * B_ * H_;

    float* xinT;  cudaGetSymbolAddress((void**)&xinT,  g_xinT);
    float* h1T;   cudaGetSymbolAddress((void**)&h1T,   g_h1T);
    float* h0T0;  cudaGetSymbolAddress((void**)&h0T0,  g_h0T0);
    float* h0T1;  cudaGetSymbolAddress((void**)&h0T1,  g_h0T1);

    dim3 grid1(CHUNKS, B_);
    attn_partial_kernel<<<grid1, 256>>>(enc, h0, c0, attW, attB);
    combine_kernel<<<B_, 256>>>(input, h0);
    xin_kernel<<<I_ / 4, 256>>>(inp_W, inp_b);
    lstm_cell_kernel<<<H_, 256>>>(xinT, h0T0, W_ih0, W_hh0, b_ih0, b_hh0,
                                  c0 + 0 * B_ * H_,
                                  out_h1, nullptr, out_c1, h1T);
    lstm_cell_kernel<<<H_, 256>>>(h1T, h0T1, W_ih1, W_hh1, b_ih1, b_hh1,
                                  c0 + 1 * B_ * H_,
                                  out_y, out_h2, out_c2, nullptr);
}